// round 4
// baseline (speedup 1.0000x reference)
#include <cuda_runtime.h>
#include <cuda_bf16.h>
#include <cstdint>
#include <math.h>

typedef __nv_bfloat16 bf16;

// Shapes: T=64, B=64, S=64, E=1024, D=1024, G=4096
// GEMM form: out[n][b] partials = sum_k W[n][k] * Z[b][k]; 3-term hi/lo bf16 mma.sync.
// Gate-interleaved weight rows: n' = d*4 + gate so each 128-row M-tile holds whole gates.

// ---------------- static device scratch ----------------
__device__ __align__(16) bf16 g_W0e_h[4096*1024], g_W0e_l[4096*1024];
__device__ __align__(16) bf16 g_Wc0_h[4096*2048], g_Wc0_l[4096*2048];
__device__ __align__(16) bf16 g_Wc1_h[4096*2048], g_Wc1_l[4096*2048];
__device__ __align__(16) bf16 g_Win_h[1024*1024], g_Win_l[1024*1024];
__device__ __align__(16) bf16 g_Wout_h[1024*2048], g_Wout_l[1024*2048];
__device__ __align__(16) bf16 g_embh[4096*1024],  g_embl[4096*1024];
__device__ __align__(16) float g_embW[64*4096*64];   // [t][n'][b]
__device__ __align__(16) float g_part[8*4096*64];    // split-K partials
__device__ __align__(16) bf16 g_Z0h[64*2048], g_Z0l[64*2048];
__device__ __align__(16) bf16 g_Z1h[64*2048], g_Z1l[64*2048];
__device__ __align__(16) bf16 g_Zoh[64*2048], g_Zol[64*2048];
__device__ __align__(16) float g_cT0[1024*64], g_cT1[1024*64];   // c in [d][b]
__device__ __align__(16) float g_bias0[4096], g_bias1[4096];     // reordered n'
__device__ int g_cnt[3][32];                                     // self-resetting

// ---------------- PTX helpers ----------------
__device__ __forceinline__ uint32_t smem_u32(const void* p) {
    uint32_t a;
    asm("{ .reg .u64 t; cvta.to.shared.u64 t, %1; cvt.u32.u64 %0, t; }" : "=r"(a) : "l"(p));
    return a;
}
__device__ __forceinline__ void ldm4(uint32_t* r, uint32_t a) {
    asm volatile("ldmatrix.sync.aligned.m8n8.x4.shared.b16 {%0,%1,%2,%3}, [%4];"
                 : "=r"(r[0]), "=r"(r[1]), "=r"(r[2]), "=r"(r[3]) : "r"(a));
}
__device__ __forceinline__ void mma_bf16(float* c, const uint32_t* a, uint32_t b0, uint32_t b1) {
    asm volatile("mma.sync.aligned.m16n8k16.row.col.f32.bf16.bf16.f32 "
                 "{%0,%1,%2,%3}, {%4,%5,%6,%7}, {%8,%9}, {%0,%1,%2,%3};"
                 : "+f"(c[0]), "+f"(c[1]), "+f"(c[2]), "+f"(c[3])
                 : "r"(a[0]), "r"(a[1]), "r"(a[2]), "r"(a[3]), "r"(b0), "r"(b1));
}
__device__ __forceinline__ void cpa16(uint32_t s, const void* g) {
    asm volatile("cp.async.cg.shared.global [%0], [%1], 16;" :: "r"(s), "l"(g));
}
#define CP_COMMIT() asm volatile("cp.async.commit_group;" ::: "memory")

__device__ __forceinline__ void hilo(float x, bf16& h, bf16& l) {
    h = __float2bfloat16(x);
    l = __float2bfloat16(x - __bfloat162float(h));
}

// ---------------- fused mma.sync GEMM ----------------
// FUSE=0: write partials only. FUSE=1: last CTA per M-tile reduces + LSTM cell.
// FUSE=2: last CTA per M-tile reduces + tanh, writes outs + next input feed.
static constexpr int PITCH = 72;
static constexpr int WBYTES = 128 * PITCH * 2;
static constexpr int ZBYTES = 64 * PITCH * 2;
static constexpr int BUFBYTES = 2 * WBYTES + 2 * ZBYTES;   // 55296
static constexpr int GEMM_SMEM = 2 * BUFBYTES;             // 110592

template <int FUSE>
__global__ void __launch_bounds__(256) gemm3k(
    const bf16* __restrict__ Wh, const bf16* __restrict__ Wl,
    const bf16* __restrict__ Zh, const bf16* __restrict__ Zl,
    int ldz, float* __restrict__ pout, int K,
    const float* __restrict__ base, const float* __restrict__ bias,
    float* __restrict__ cT,
    bf16* hAh, bf16* hAl, int offA,
    bf16* hBh, bf16* hBl, int offB,
    float* __restrict__ out_t, int* __restrict__ cnt)
{
    extern __shared__ __align__(16) char dsm[];
    const int tid  = threadIdx.x;
    const int lane = tid & 31, wid = tid >> 5;
    const int wm = wid >> 1, wn = wid & 1;
    const int Nrows = gridDim.x * 128;
    const int n0 = blockIdx.x * 128;
    const int KS = gridDim.y;
    const int Kc = K / KS;
    const int k0 = blockIdx.y * Kc;
    const int chunks = Kc / 64;

    const bf16* Zh_ = Zh + (size_t)blockIdx.z * 64 * ldz;
    const bf16* Zl_ = Zl + (size_t)blockIdx.z * 64 * ldz;
    float* out = pout + (size_t)(blockIdx.z * KS + blockIdx.y) * Nrows * 64;

    const uint32_t sb = smem_u32(dsm);

    float acc[2][4][4];
#pragma unroll
    for (int mi = 0; mi < 2; mi++)
#pragma unroll
        for (int j = 0; j < 4; j++)
#pragma unroll
            for (int q = 0; q < 4; q++) acc[mi][j][q] = 0.f;

    auto stage = [&](int c) {
        const uint32_t S = sb + (c & 1) * BUFBYTES;
        const int kb = k0 + c * 64;
#pragma unroll
        for (int i = 0; i < 4; i++) {
            int idx = i * 256 + tid;
            int row = idx >> 3, cg = idx & 7;
            size_t g = (size_t)(n0 + row) * K + kb + cg * 8;
            uint32_t d = S + (row * PITCH + cg * 8) * 2;
            cpa16(d, Wh + g);
            cpa16(d + WBYTES, Wl + g);
        }
#pragma unroll
        for (int i = 0; i < 2; i++) {
            int idx = i * 256 + tid;
            int row = idx >> 3, cg = idx & 7;
            size_t g = (size_t)row * ldz + kb + cg * 8;
            uint32_t d = S + 2 * WBYTES + (row * PITCH + cg * 8) * 2;
            cpa16(d, Zh_ + g);
            cpa16(d + ZBYTES, Zl_ + g);
        }
        CP_COMMIT();
    };

    stage(0);
    for (int c = 0; c < chunks; c++) {
        if (c + 1 < chunks) {
            stage(c + 1);
            asm volatile("cp.async.wait_group 1;" ::: "memory");
        } else {
            asm volatile("cp.async.wait_group 0;" ::: "memory");
        }
        __syncthreads();

        const uint32_t S = sb + (c & 1) * BUFBYTES;
        const uint32_t aw = S + ((wm * 32 + (lane & 15)) * PITCH + (lane >> 4) * 8) * 2;
        const uint32_t bz = S + 2 * WBYTES + ((wn * 32 + (lane & 15)) * PITCH + (lane >> 4) * 8) * 2;

#pragma unroll
        for (int ks = 0; ks < 4; ks++) {
            const uint32_t koff = ks * 32;
            uint32_t ah[2][4], al[2][4], bh[2][4], bl[2][4];
#pragma unroll
            for (int mi = 0; mi < 2; mi++) {
                uint32_t a = aw + mi * 16 * PITCH * 2 + koff;
                ldm4(ah[mi], a);
                ldm4(al[mi], a + WBYTES);
            }
#pragma unroll
            for (int bi = 0; bi < 2; bi++) {
                uint32_t a = bz + bi * 16 * PITCH * 2 + koff;
                ldm4(bh[bi], a);
                ldm4(bl[bi], a + ZBYTES);
            }
#pragma unroll
            for (int mi = 0; mi < 2; mi++)
#pragma unroll
                for (int j = 0; j < 4; j++) {
                    int bi = j >> 1, s = j & 1;
                    mma_bf16(acc[mi][j], ah[mi], bh[bi][s], bh[bi][2 + s]);
                    mma_bf16(acc[mi][j], ah[mi], bl[bi][s], bl[bi][2 + s]);
                    mma_bf16(acc[mi][j], al[mi], bh[bi][s], bh[bi][2 + s]);
                }
        }
        __syncthreads();
    }

    // write partials
#pragma unroll
    for (int mi = 0; mi < 2; mi++)
#pragma unroll
        for (int j = 0; j < 4; j++) {
            int m = n0 + wm * 32 + mi * 16 + (lane >> 2);
            int b = wn * 32 + j * 8 + (lane & 3) * 2;
            *(float2*)(out + (size_t)m * 64 + b) =
                make_float2(acc[mi][j][0], acc[mi][j][1]);
            *(float2*)(out + (size_t)(m + 8) * 64 + b) =
                make_float2(acc[mi][j][2], acc[mi][j][3]);
        }

    if (FUSE == 0) return;

    // ---- last-CTA-per-M-tile reduction + fused consumer ----
    __threadfence();
    __syncthreads();
    __shared__ int s_last;
    if (tid == 0) {
        int old = atomicAdd(&cnt[blockIdx.x], 1);
        int last = (old == KS - 1);
        if (last) cnt[blockIdx.x] = 0;
        s_last = last;
    }
    __syncthreads();
    if (!s_last) return;
    __threadfence();

    if (FUSE == 1) {
        float* sred = (float*)dsm;   // 128 x 64
        for (int idx = tid; idx < 8192; idx += 256) {
            int row = idx >> 6, b = idx & 63;
            int n = n0 + row;
            float a = bias[n];
            if (base) a += base[(size_t)n * 64 + b];
            for (int ks = 0; ks < KS; ks++)
                a += pout[((size_t)ks * Nrows + n) * 64 + b];
            sred[idx] = a;
        }
        __syncthreads();
        for (int idx = tid; idx < 2048; idx += 256) {
            int dd = idx >> 6, b = idx & 63;
            int d = (n0 >> 2) + dd;
            float gi = sred[(dd * 4 + 0) * 64 + b];
            float gf = sred[(dd * 4 + 1) * 64 + b];
            float gg = sred[(dd * 4 + 2) * 64 + b];
            float go = sred[(dd * 4 + 3) * 64 + b];
            float ig = 1.f / (1.f + expf(-gi));
            float fg = 1.f / (1.f + expf(-gf));
            float g2 = tanhf(gg);
            float og = 1.f / (1.f + expf(-go));
            float cn = fg * cT[d * 64 + b] + ig * g2;
            float h  = og * tanhf(cn);
            cT[d * 64 + b] = cn;
            bf16 hh, hl;
            hilo(h, hh, hl);
            hAh[b * 2048 + offA + d] = hh; hAl[b * 2048 + offA + d] = hl;
            hBh[b * 2048 + offB + d] = hh; hBl[b * 2048 + offB + d] = hl;
        }
    } else {  // FUSE == 2: tanh output + next input feed
        for (int idx = tid; idx < 8192; idx += 256) {
            int row = idx >> 6, b = idx & 63;
            int n = n0 + row;
            float a = 0.f;
            for (int ks = 0; ks < KS; ks++)
                a += pout[((size_t)ks * Nrows + n) * 64 + b];
            float h = tanhf(a);
            out_t[b * 1024 + n] = h;
            bf16 hh, hl;
            hilo(h, hh, hl);
            hAh[b * 2048 + offA + n] = hh;
            hAl[b * 2048 + offA + n] = hl;
        }
    }
}

// ---------------- attention ----------------
__global__ void attention_k(const float* __restrict__ part, int KS,
                            const float* __restrict__ ctx,   // [S,B,D]
                            float* __restrict__ attns_t,     // [B,S]
                            bf16* __restrict__ zoh, bf16* __restrict__ zol)
{
    __shared__ float qs[1024];
    __shared__ float sc[64];
    int b = blockIdx.x, tid = threadIdx.x;
    for (int d = tid; d < 1024; d += 256) {
        float acc = 0.f;
        for (int ks = 0; ks < KS; ks++)
            acc += part[((size_t)ks * 1024 + d) * 64 + b];
        qs[d] = acc;
    }
    __syncthreads();
    int w = tid >> 5, lane = tid & 31;
    for (int so = 0; so < 8; so++) {
        int s = w * 8 + so;
        const float* cr = ctx + ((size_t)s * 64 + b) * 1024;
        float acc = 0.f;
        for (int d = lane; d < 1024; d += 32) acc += qs[d] * cr[d];
#pragma unroll
        for (int off = 16; off; off >>= 1) acc += __shfl_down_sync(0xffffffffu, acc, off);
        if (lane == 0) sc[s] = acc;
    }
    __syncthreads();
    if (tid < 32) {
        float v0 = sc[tid], v1 = sc[tid + 32];
        float m = fmaxf(v0, v1);
#pragma unroll
        for (int off = 16; off; off >>= 1) m = fmaxf(m, __shfl_xor_sync(0xffffffffu, m, off));
        float e0 = expf(v0 - m), e1 = expf(v1 - m);
        float s = e0 + e1;
#pragma unroll
        for (int off = 16; off; off >>= 1) s += __shfl_xor_sync(0xffffffffu, s, off);
        float inv = 1.f / s;
        float a0 = e0 * inv, a1 = e1 * inv;
        sc[tid] = a0; sc[tid + 32] = a1;
        attns_t[b * 64 + tid] = a0;
        attns_t[b * 64 + tid + 32] = a1;
    }
    __syncthreads();
    for (int d = tid; d < 1024; d += 256) {
        float acc = 0.f;
#pragma unroll 8
        for (int s = 0; s < 64; s++)
            acc += sc[s] * ctx[((size_t)s * 64 + b) * 1024 + d];
        bf16 hh, hl;
        hilo(acc, hh, hl);
        zoh[b * 2048 + d] = hh;
        zol[b * 2048 + d] = hl;
    }
}

// ---------------- init state ----------------
__global__ void init_state(const float* __restrict__ input_feed,
                           const float* __restrict__ h0, const float* __restrict__ c0)
{
    int e = blockIdx.x * blockDim.x + threadIdx.x;  // 65536
    int b = e >> 10, d = e & 1023;
    bf16 hh, hl;
    hilo(input_feed[e], hh, hl);
    g_Z0h[b * 2048 + d] = hh; g_Z0l[b * 2048 + d] = hl;
    hilo(h0[e], hh, hl);
    g_Z0h[b * 2048 + 1024 + d] = hh; g_Z0l[b * 2048 + 1024 + d] = hl;
    hilo(h0[65536 + e], hh, hl);
    g_Z1h[b * 2048 + 1024 + d] = hh; g_Z1l[b * 2048 + 1024 + d] = hl;
    g_cT0[d * 64 + b] = c0[e];
    g_cT1[d * 64 + b] = c0[65536 + e];
}

// ---------------- weight prep (hi/lo conversion + gate-interleave reorder) ----------------
__global__ void prep_w(const float* __restrict__ W_ih0, const float* __restrict__ W_hh0,
                       const float* __restrict__ W_ih1, const float* __restrict__ W_hh1,
                       const float* __restrict__ W_in,  const float* __restrict__ W_out,
                       const float* __restrict__ emb,
                       const float* __restrict__ b_ih0, const float* __restrict__ b_hh0,
                       const float* __restrict__ b_ih1, const float* __restrict__ b_hh1)
{
    size_t stride = (size_t)gridDim.x * blockDim.x;
    for (size_t i = (size_t)blockIdx.x * blockDim.x + threadIdx.x;
         i < 4096ull * 2048ull; i += stride) {
        size_t n = i >> 11, k = i & 2047;
        size_t np = (size_t)((n & 1023) * 4 + (n >> 10));     // gate interleave
        float v0 = (k < 1024) ? W_ih0[n * 2048 + 1024 + k] : W_hh0[n * 1024 + (k - 1024)];
        hilo(v0, g_Wc0_h[np * 2048 + k], g_Wc0_l[np * 2048 + k]);
        float v1 = (k < 1024) ? W_ih1[n * 1024 + k] : W_hh1[n * 1024 + (k - 1024)];
        hilo(v1, g_Wc1_h[np * 2048 + k], g_Wc1_l[np * 2048 + k]);
        if (n < 1024) hilo(W_out[i], g_Wout_h[i], g_Wout_l[i]);
        if (i < 4096ull * 1024ull) {
            size_t nn = i >> 10, kk = i & 1023;
            size_t np2 = (nn & 1023) * 4 + (nn >> 10);
            hilo(W_ih0[nn * 2048 + kk], g_W0e_h[np2 * 1024 + kk], g_W0e_l[np2 * 1024 + kk]);
            hilo(emb[i], g_embh[i], g_embl[i]);
        }
        if (i < 1024ull * 1024ull) hilo(W_in[i], g_Win_h[i], g_Win_l[i]);
        if (i < 4096) {
            size_t np3 = (i & 1023) * 4 + (i >> 10);
            g_bias0[np3] = b_ih0[i] + b_hh0[i];
            g_bias1[np3] = b_ih1[i] + b_hh1[i];
        }
    }
}

// ---------------- host orchestration ----------------
extern "C" void kernel_launch(void* const* d_in, const int* in_sizes, int n_in,
                              void* d_out, int out_size)
{
    (void)in_sizes; (void)n_in; (void)out_size;
    const float* emb        = (const float*)d_in[0];
    const float* context    = (const float*)d_in[1];
    const float* input_feed = (const float*)d_in[2];
    const float* h0         = (const float*)d_in[3];
    const float* c0         = (const float*)d_in[4];
    const float* W_ih0      = (const float*)d_in[5];
    const float* W_hh0      = (const float*)d_in[6];
    const float* b_ih0      = (const float*)d_in[7];
    const float* b_hh0      = (const float*)d_in[8];
    const float* W_ih1      = (const float*)d_in[9];
    const float* W_hh1      = (const float*)d_in[10];
    const float* b_ih1      = (const float*)d_in[11];
    const float* b_hh1      = (const float*)d_in[12];
    const float* W_in       = (const float*)d_in[13];
    const float* W_out      = (const float*)d_in[14];

    float* outs  = (float*)d_out;
    float* attns = outs + 64 * 64 * 1024;

    static bool attr_set = false;
    if (!attr_set) {
        cudaFuncSetAttribute(gemm3k<0>, cudaFuncAttributeMaxDynamicSharedMemorySize, GEMM_SMEM);
        cudaFuncSetAttribute(gemm3k<1>, cudaFuncAttributeMaxDynamicSharedMemorySize, GEMM_SMEM);
        cudaFuncSetAttribute(gemm3k<2>, cudaFuncAttributeMaxDynamicSharedMemorySize, GEMM_SMEM);
        attr_set = true;
    }

    bf16 *pW0eh, *pW0el, *pWc0h, *pWc0l, *pWc1h, *pWc1l,
         *pWinh, *pWinl, *pWouth, *pWoutl, *pEh, *pEl,
         *pZ0h, *pZ0l, *pZ1h, *pZ1l, *pZoh, *pZol;
    float *pEmbW, *pPart, *pC0, *pC1, *pB0, *pB1;
    int* pCnt;
    cudaGetSymbolAddress((void**)&pW0eh, g_W0e_h);  cudaGetSymbolAddress((void**)&pW0el, g_W0e_l);
    cudaGetSymbolAddress((void**)&pWc0h, g_Wc0_h);  cudaGetSymbolAddress((void**)&pWc0l, g_Wc0_l);
    cudaGetSymbolAddress((void**)&pWc1h, g_Wc1_h);  cudaGetSymbolAddress((void**)&pWc1l, g_Wc1_l);
    cudaGetSymbolAddress((void**)&pWinh, g_Win_h);  cudaGetSymbolAddress((void**)&pWinl, g_Win_l);
    cudaGetSymbolAddress((void**)&pWouth, g_Wout_h); cudaGetSymbolAddress((void**)&pWoutl, g_Wout_l);
    cudaGetSymbolAddress((void**)&pEh, g_embh);      cudaGetSymbolAddress((void**)&pEl, g_embl);
    cudaGetSymbolAddress((void**)&pZ0h, g_Z0h);      cudaGetSymbolAddress((void**)&pZ0l, g_Z0l);
    cudaGetSymbolAddress((void**)&pZ1h, g_Z1h);      cudaGetSymbolAddress((void**)&pZ1l, g_Z1l);
    cudaGetSymbolAddress((void**)&pZoh, g_Zoh);      cudaGetSymbolAddress((void**)&pZol, g_Zol);
    cudaGetSymbolAddress((void**)&pEmbW, g_embW);
    cudaGetSymbolAddress((void**)&pPart, g_part);
    cudaGetSymbolAddress((void**)&pC0, g_cT0);       cudaGetSymbolAddress((void**)&pC1, g_cT1);
    cudaGetSymbolAddress((void**)&pB0, g_bias0);     cudaGetSymbolAddress((void**)&pB1, g_bias1);
    cudaGetSymbolAddress((void**)&pCnt, g_cnt);

    prep_w<<<4096, 256>>>(W_ih0, W_hh0, W_ih1, W_hh1, W_in, W_out, emb,
                          b_ih0, b_hh0, b_ih1, b_hh1);
    init_state<<<256, 256>>>(input_feed, h0, c0);
    // embW[t][n'][b] = emb_t @ W0e^T (reordered rows, bias added later in cell)
    gemm3k<0><<<dim3(32, 1, 64), 256, GEMM_SMEM>>>(
        pW0eh, pW0el, pEh, pEl, 1024, pEmbW, 1024,
        nullptr, nullptr, nullptr, nullptr, nullptr, 0, nullptr, nullptr, 0, nullptr, nullptr);

    for (int t = 0; t < 64; t++) {
        // LSTM layer 0 (fused cell)
        gemm3k<1><<<dim3(32, 8, 1), 256, GEMM_SMEM>>>(
            pWc0h, pWc0l, pZ0h, pZ0l, 2048, pPart, 2048,
            pEmbW + (size_t)t * 4096 * 64, pB0, pC0,
            pZ1h, pZ1l, 0, pZ0h, pZ0l, 1024, nullptr, pCnt + 0 * 32);
        // LSTM layer 1 (fused cell)
        gemm3k<1><<<dim3(32, 8, 1), 256, GEMM_SMEM>>>(
            pWc1h, pWc1l, pZ1h, pZ1l, 2048, pPart, 2048,
            nullptr, pB1, pC1,
            pZoh, pZol, 1024, pZ1h, pZ1l, 1024, nullptr, pCnt + 1 * 32);
        // q = h1 @ W_in^T (partials only)
        gemm3k<0><<<dim3(8, 16, 1), 256, GEMM_SMEM>>>(
            pWinh, pWinl, pZoh + 1024, pZol + 1024, 2048, pPart, 1024,
            nullptr, nullptr, nullptr, nullptr, nullptr, 0, nullptr, nullptr, 0, nullptr, nullptr);
        // attention
        attention_k<<<64, 256>>>(pPart, 16, context, attns + (size_t)t * 64 * 64, pZoh, pZol);
        // attn_h = tanh([cvec|h1] @ W_out^T) (fused tanh + feed)
        gemm3k<2><<<dim3(8, 16, 1), 256, GEMM_SMEM>>>(
            pWouth, pWoutl, pZoh, pZol, 2048, pPart, 2048,
            nullptr, nullptr, nullptr,
            pZ0h, pZ0l, 0, nullptr, nullptr, 0,
            outs + (size_t)t * 64 * 1024, pCnt + 2 * 32);
    }
}

// round 5
// speedup vs baseline: 2.0939x; 2.0939x over previous
#include <cuda_runtime.h>
#include <cuda_bf16.h>
#include <cstdint>
#include <math.h>

typedef __nv_bfloat16 bf16;

// Shapes: T=64, B=64, S=64, E=1024, D=1024, G=4096
// GEMM form: out[n][b] (split-K partials) = sum_k W[n][k] * Z[b][k]
// 3-term hi/lo bf16 via mma.sync.m16n8k16, fp32 accumulation.
// 512-thread CTAs, 4x4 warp grid (each warp 32Mx16N) for 4 warps/SMSP.

// ---------------- static device scratch ----------------
__device__ __align__(16) bf16 g_W0e_h[4096*1024], g_W0e_l[4096*1024];
__device__ __align__(16) bf16 g_Wc0_h[4096*2048], g_Wc0_l[4096*2048];
__device__ __align__(16) bf16 g_Wc1_h[4096*2048], g_Wc1_l[4096*2048];
__device__ __align__(16) bf16 g_Win_h[1024*1024], g_Win_l[1024*1024];
__device__ __align__(16) bf16 g_Wout_h[1024*2048], g_Wout_l[1024*2048];
__device__ __align__(16) bf16 g_embh[4096*1024],  g_embl[4096*1024];
__device__ __align__(16) float g_embW[64*4096*64];   // [t][n][b]
__device__ __align__(16) float g_part[8*4096*64];    // split-K partials [ks][n][b]
__device__ __align__(16) bf16 g_Z0h[64*2048], g_Z0l[64*2048];
__device__ __align__(16) bf16 g_Z1h[64*2048], g_Z1l[64*2048];
__device__ __align__(16) bf16 g_Zoh[64*2048], g_Zol[64*2048];
__device__ __align__(16) float g_cT0[1024*64], g_cT1[1024*64];
__device__ __align__(16) float g_bias0[4096], g_bias1[4096];

// ---------------- PTX helpers ----------------
__device__ __forceinline__ uint32_t smem_u32(const void* p) {
    uint32_t a;
    asm("{ .reg .u64 t; cvta.to.shared.u64 t, %1; cvt.u32.u64 %0, t; }" : "=r"(a) : "l"(p));
    return a;
}
__device__ __forceinline__ void ldm4(uint32_t* r, uint32_t a) {
    asm volatile("ldmatrix.sync.aligned.m8n8.x4.shared.b16 {%0,%1,%2,%3}, [%4];"
                 : "=r"(r[0]), "=r"(r[1]), "=r"(r[2]), "=r"(r[3]) : "r"(a));
}
__device__ __forceinline__ void mma_bf16(float* c, const uint32_t* a, uint32_t b0, uint32_t b1) {
    asm volatile("mma.sync.aligned.m16n8k16.row.col.f32.bf16.bf16.f32 "
                 "{%0,%1,%2,%3}, {%4,%5,%6,%7}, {%8,%9}, {%0,%1,%2,%3};"
                 : "+f"(c[0]), "+f"(c[1]), "+f"(c[2]), "+f"(c[3])
                 : "r"(a[0]), "r"(a[1]), "r"(a[2]), "r"(a[3]), "r"(b0), "r"(b1));
}
__device__ __forceinline__ void cpa16(uint32_t s, const void* g) {
    asm volatile("cp.async.cg.shared.global [%0], [%1], 16;" :: "r"(s), "l"(g));
}
#define CP_COMMIT() asm volatile("cp.async.commit_group;" ::: "memory")

__device__ __forceinline__ void hilo(float x, bf16& h, bf16& l) {
    h = __float2bfloat16(x);
    l = __float2bfloat16(x - __bfloat162float(h));
}

// ---------------- mma.sync GEMM (512 threads, 4x4 warp grid) ----------------
static constexpr int PITCH = 72;                    // bf16 elems; 144B rows
static constexpr int WBYTES = 128 * PITCH * 2;      // 18432
static constexpr int ZBYTES = 64 * PITCH * 2;       // 9216
static constexpr int BUFBYTES = 2 * WBYTES + 2 * ZBYTES;  // 55296
static constexpr int GEMM_SMEM = 2 * BUFBYTES;            // 110592

__global__ void __launch_bounds__(512) gemm3(
    const bf16* __restrict__ Wh, const bf16* __restrict__ Wl,
    const bf16* __restrict__ Zh, const bf16* __restrict__ Zl,
    int ldz, float* __restrict__ out, int K)
{
    extern __shared__ __align__(16) char dsm[];
    const int tid  = threadIdx.x;
    const int lane = tid & 31, wid = tid >> 5;      // wid 0..15
    const int wm = wid >> 2, wn = wid & 3;          // 4x4 warp grid
    const int Nrows = gridDim.x * 128;
    const int n0 = blockIdx.x * 128;
    const int Kc = K / gridDim.y;
    const int k0 = blockIdx.y * Kc;
    const int chunks = Kc / 64;

    Zh += (size_t)blockIdx.z * 64 * ldz;
    Zl += (size_t)blockIdx.z * 64 * ldz;
    out += (size_t)(blockIdx.z * gridDim.y + blockIdx.y) * Nrows * 64;

    const uint32_t sb = smem_u32(dsm);

    float acc[2][2][4];
#pragma unroll
    for (int mi = 0; mi < 2; mi++)
#pragma unroll
        for (int nj = 0; nj < 2; nj++)
#pragma unroll
            for (int q = 0; q < 4; q++) acc[mi][nj][q] = 0.f;

    // ---- stage chunk c into buffer c&1 ----
    auto stage = [&](int c) {
        const uint32_t S = sb + (c & 1) * BUFBYTES;
        const int kb = k0 + c * 64;
#pragma unroll
        for (int i = 0; i < 2; i++) {
            int idx = i * 512 + tid;
            int row = idx >> 3, cg = idx & 7;
            size_t g = (size_t)(n0 + row) * K + kb + cg * 8;
            uint32_t d = S + (row * PITCH + cg * 8) * 2;
            cpa16(d, Wh + g);
            cpa16(d + WBYTES, Wl + g);
        }
        {
            int row = tid >> 3, cg = tid & 7;
            size_t g = (size_t)row * ldz + kb + cg * 8;
            uint32_t d = S + 2 * WBYTES + (row * PITCH + cg * 8) * 2;
            cpa16(d, Zh + g);
            cpa16(d + ZBYTES, Zl + g);
        }
        CP_COMMIT();
    };

    stage(0);
    for (int c = 0; c < chunks; c++) {
        if (c + 1 < chunks) {
            stage(c + 1);
            asm volatile("cp.async.wait_group 1;" ::: "memory");
        } else {
            asm volatile("cp.async.wait_group 0;" ::: "memory");
        }
        __syncthreads();

        const uint32_t S = sb + (c & 1) * BUFBYTES;
        const uint32_t aw = S + ((wm * 32 + (lane & 15)) * PITCH + (lane >> 4) * 8) * 2;
        const uint32_t bz = S + 2 * WBYTES + ((wn * 16 + (lane & 15)) * PITCH + (lane >> 4) * 8) * 2;

#pragma unroll
        for (int ks = 0; ks < 4; ks++) {
            const uint32_t koff = ks * 32;
            uint32_t ah[2][4], al[2][4], bh[4], bl[4];
#pragma unroll
            for (int mi = 0; mi < 2; mi++) {
                uint32_t a = aw + mi * 16 * PITCH * 2 + koff;
                ldm4(ah[mi], a);
                ldm4(al[mi], a + WBYTES);
            }
            ldm4(bh, bz + koff);
            ldm4(bl, bz + koff + ZBYTES);
#pragma unroll
            for (int mi = 0; mi < 2; mi++)
#pragma unroll
                for (int nj = 0; nj < 2; nj++) {
                    mma_bf16(acc[mi][nj], ah[mi], bh[nj], bh[2 + nj]);
                    mma_bf16(acc[mi][nj], ah[mi], bl[nj], bl[2 + nj]);
                    mma_bf16(acc[mi][nj], al[mi], bh[nj], bh[2 + nj]);
                }
        }
        __syncthreads();
    }

    // epilogue: m16n8 C frag layout
#pragma unroll
    for (int mi = 0; mi < 2; mi++)
#pragma unroll
        for (int nj = 0; nj < 2; nj++) {
            int m = n0 + wm * 32 + mi * 16 + (lane >> 2);
            int b = wn * 16 + nj * 8 + (lane & 3) * 2;
            *(float2*)(out + (size_t)m * 64 + b) =
                make_float2(acc[mi][nj][0], acc[mi][nj][1]);
            *(float2*)(out + (size_t)(m + 8) * 64 + b) =
                make_float2(acc[mi][nj][2], acc[mi][nj][3]);
        }
}

// ---------------- LSTM cell: reduce partials, apply gates ----------------
__global__ void lstm_cell(const float* __restrict__ part, int KS,
                          const float* __restrict__ base,   // [n][b] or null
                          const float* __restrict__ bias,   // [4096]
                          float* __restrict__ cT,
                          bf16* hAh, bf16* hAl, int offA,
                          bf16* hBh, bf16* hBl, int offB)
{
    int e = blockIdx.x * blockDim.x + threadIdx.x;   // e = d*64 + b
    int d = e >> 6, b = e & 63;
    float g[4];
#pragma unroll
    for (int j = 0; j < 4; j++) {
        float acc = bias[j * 1024 + d];
        if (base) acc += base[(size_t)j * 65536 + e];
        for (int ks = 0; ks < KS; ks++)
            acc += part[(size_t)ks * 262144 + (size_t)j * 65536 + e];
        g[j] = acc;
    }
    float ig = 1.f / (1.f + expf(-g[0]));
    float fg = 1.f / (1.f + expf(-g[1]));
    float gg = tanhf(g[2]);
    float og = 1.f / (1.f + expf(-g[3]));
    float cn = fg * cT[e] + ig * gg;
    float h  = og * tanhf(cn);
    cT[e] = cn;
    bf16 hh, hl;
    hilo(h, hh, hl);
    hAh[b * 2048 + offA + d] = hh; hAl[b * 2048 + offA + d] = hl;
    hBh[b * 2048 + offB + d] = hh; hBl[b * 2048 + offB + d] = hl;
}

// ---------------- attention ----------------
__global__ void attention_k(const float* __restrict__ part, int KS,
                            const float* __restrict__ ctx,   // [S,B,D]
                            float* __restrict__ attns_t,     // [B,S]
                            bf16* __restrict__ zoh, bf16* __restrict__ zol)
{
    __shared__ float qs[1024];
    __shared__ float sc[64];
    int b = blockIdx.x, tid = threadIdx.x;
    for (int d = tid; d < 1024; d += 256) {
        float acc = 0.f;
        for (int ks = 0; ks < KS; ks++)
            acc += part[((size_t)ks * 1024 + d) * 64 + b];
        qs[d] = acc;
    }
    __syncthreads();
    int w = tid >> 5, lane = tid & 31;
    for (int so = 0; so < 8; so++) {
        int s = w * 8 + so;
        const float* cr = ctx + ((size_t)s * 64 + b) * 1024;
        float acc = 0.f;
        for (int d = lane; d < 1024; d += 32) acc += qs[d] * cr[d];
#pragma unroll
        for (int off = 16; off; off >>= 1) acc += __shfl_down_sync(0xffffffffu, acc, off);
        if (lane == 0) sc[s] = acc;
    }
    __syncthreads();
    if (tid < 32) {
        float v0 = sc[tid], v1 = sc[tid + 32];
        float m = fmaxf(v0, v1);
#pragma unroll
        for (int off = 16; off; off >>= 1) m = fmaxf(m, __shfl_xor_sync(0xffffffffu, m, off));
        float e0 = expf(v0 - m), e1 = expf(v1 - m);
        float s = e0 + e1;
#pragma unroll
        for (int off = 16; off; off >>= 1) s += __shfl_xor_sync(0xffffffffu, s, off);
        float inv = 1.f / s;
        float a0 = e0 * inv, a1 = e1 * inv;
        sc[tid] = a0; sc[tid + 32] = a1;
        attns_t[b * 64 + tid] = a0;
        attns_t[b * 64 + tid + 32] = a1;
    }
    __syncthreads();
    for (int d = tid; d < 1024; d += 256) {
        float acc = 0.f;
#pragma unroll 8
        for (int s = 0; s < 64; s++)
            acc += sc[s] * ctx[((size_t)s * 64 + b) * 1024 + d];
        bf16 hh, hl;
        hilo(acc, hh, hl);
        zoh[b * 2048 + d] = hh;
        zol[b * 2048 + d] = hl;
    }
}

// ---------------- output tanh + next input feed ----------------
__global__ void attn_out(const float* __restrict__ part, int KS,
                         float* __restrict__ out_t,
                         bf16* __restrict__ z0h, bf16* __restrict__ z0l)
{
    int e = blockIdx.x * blockDim.x + threadIdx.x;  // e = d*64 + b
    int d = e >> 6, b = e & 63;
    float acc = 0.f;
    for (int ks = 0; ks < KS; ks++)
        acc += part[(size_t)ks * 65536 + e];
    float h = tanhf(acc);
    out_t[b * 1024 + d] = h;
    bf16 hh, hl;
    hilo(h, hh, hl);
    z0h[b * 2048 + d] = hh;
    z0l[b * 2048 + d] = hl;
}

// ---------------- init state ----------------
__global__ void init_state(const float* __restrict__ input_feed,
                           const float* __restrict__ h0, const float* __restrict__ c0)
{
    int e = blockIdx.x * blockDim.x + threadIdx.x;  // 65536
    int b = e >> 10, d = e & 1023;
    bf16 hh, hl;
    hilo(input_feed[e], hh, hl);
    g_Z0h[b * 2048 + d] = hh; g_Z0l[b * 2048 + d] = hl;
    hilo(h0[e], hh, hl);
    g_Z0h[b * 2048 + 1024 + d] = hh; g_Z0l[b * 2048 + 1024 + d] = hl;
    hilo(h0[65536 + e], hh, hl);
    g_Z1h[b * 2048 + 1024 + d] = hh; g_Z1l[b * 2048 + 1024 + d] = hl;
    g_cT0[d * 64 + b] = c0[e];
    g_cT1[d * 64 + b] = c0[65536 + e];
}

// ---------------- weight prep (hi/lo conversion + packing) ----------------
__global__ void prep_w(const float* __restrict__ W_ih0, const float* __restrict__ W_hh0,
                       const float* __restrict__ W_ih1, const float* __restrict__ W_hh1,
                       const float* __restrict__ W_in,  const float* __restrict__ W_out,
                       const float* __restrict__ emb,
                       const float* __restrict__ b_ih0, const float* __restrict__ b_hh0,
                       const float* __restrict__ b_ih1, const float* __restrict__ b_hh1)
{
    size_t stride = (size_t)gridDim.x * blockDim.x;
    for (size_t i = (size_t)blockIdx.x * blockDim.x + threadIdx.x;
         i < 4096ull * 2048ull; i += stride) {
        size_t n = i >> 11, k = i & 2047;
        float v0 = (k < 1024) ? W_ih0[n * 2048 + 1024 + k] : W_hh0[n * 1024 + (k - 1024)];
        hilo(v0, g_Wc0_h[i], g_Wc0_l[i]);
        float v1 = (k < 1024) ? W_ih1[n * 1024 + k] : W_hh1[n * 1024 + (k - 1024)];
        hilo(v1, g_Wc1_h[i], g_Wc1_l[i]);
        if (n < 1024) hilo(W_out[i], g_Wout_h[i], g_Wout_l[i]);
        if (i < 4096ull * 1024ull) {
            size_t nn = i >> 10, kk = i & 1023;
            hilo(W_ih0[nn * 2048 + kk], g_W0e_h[i], g_W0e_l[i]);
            hilo(emb[i], g_embh[i], g_embl[i]);
        }
        if (i < 1024ull * 1024ull) hilo(W_in[i], g_Win_h[i], g_Win_l[i]);
        if (i < 4096) {
            g_bias0[i] = b_ih0[i] + b_hh0[i];
            g_bias1[i] = b_ih1[i] + b_hh1[i];
        }
    }
}

// ---------------- host orchestration ----------------
extern "C" void kernel_launch(void* const* d_in, const int* in_sizes, int n_in,
                              void* d_out, int out_size)
{
    (void)in_sizes; (void)n_in; (void)out_size;
    const float* emb        = (const float*)d_in[0];
    const float* context    = (const float*)d_in[1];
    const float* input_feed = (const float*)d_in[2];
    const float* h0         = (const float*)d_in[3];
    const float* c0         = (const float*)d_in[4];
    const float* W_ih0      = (const float*)d_in[5];
    const float* W_hh0      = (const float*)d_in[6];
    const float* b_ih0      = (const float*)d_in[7];
    const float* b_hh0      = (const float*)d_in[8];
    const float* W_ih1      = (const float*)d_in[9];
    const float* W_hh1      = (const float*)d_in[10];
    const float* b_ih1      = (const float*)d_in[11];
    const float* b_hh1      = (const float*)d_in[12];
    const float* W_in       = (const float*)d_in[13];
    const float* W_out      = (const float*)d_in[14];

    float* outs  = (float*)d_out;
    float* attns = outs + 64 * 64 * 1024;

    static bool attr_set = false;
    if (!attr_set) {
        cudaFuncSetAttribute(gemm3, cudaFuncAttributeMaxDynamicSharedMemorySize, GEMM_SMEM);
        attr_set = true;
    }

    bf16 *pW0eh, *pW0el, *pWc0h, *pWc0l, *pWc1h, *pWc1l,
         *pWinh, *pWinl, *pWouth, *pWoutl, *pEh, *pEl,
         *pZ0h, *pZ0l, *pZ1h, *pZ1l, *pZoh, *pZol;
    float *pEmbW, *pPart, *pC0, *pC1, *pB0, *pB1;
    cudaGetSymbolAddress((void**)&pW0eh, g_W0e_h);  cudaGetSymbolAddress((void**)&pW0el, g_W0e_l);
    cudaGetSymbolAddress((void**)&pWc0h, g_Wc0_h);  cudaGetSymbolAddress((void**)&pWc0l, g_Wc0_l);
    cudaGetSymbolAddress((void**)&pWc1h, g_Wc1_h);  cudaGetSymbolAddress((void**)&pWc1l, g_Wc1_l);
    cudaGetSymbolAddress((void**)&pWinh, g_Win_h);  cudaGetSymbolAddress((void**)&pWinl, g_Win_l);
    cudaGetSymbolAddress((void**)&pWouth, g_Wout_h); cudaGetSymbolAddress((void**)&pWoutl, g_Wout_l);
    cudaGetSymbolAddress((void**)&pEh, g_embh);      cudaGetSymbolAddress((void**)&pEl, g_embl);
    cudaGetSymbolAddress((void**)&pZ0h, g_Z0h);      cudaGetSymbolAddress((void**)&pZ0l, g_Z0l);
    cudaGetSymbolAddress((void**)&pZ1h, g_Z1h);      cudaGetSymbolAddress((void**)&pZ1l, g_Z1l);
    cudaGetSymbolAddress((void**)&pZoh, g_Zoh);      cudaGetSymbolAddress((void**)&pZol, g_Zol);
    cudaGetSymbolAddress((void**)&pEmbW, g_embW);
    cudaGetSymbolAddress((void**)&pPart, g_part);
    cudaGetSymbolAddress((void**)&pC0, g_cT0);       cudaGetSymbolAddress((void**)&pC1, g_cT1);
    cudaGetSymbolAddress((void**)&pB0, g_bias0);     cudaGetSymbolAddress((void**)&pB1, g_bias1);

    prep_w<<<4096, 256>>>(W_ih0, W_hh0, W_ih1, W_hh1, W_in, W_out, emb,
                          b_ih0, b_hh0, b_ih1, b_hh1);
    init_state<<<256, 256>>>(input_feed, h0, c0);
    // embW[t][n][b] = emb_t @ W_ih0[:, :1024]^T
    gemm3<<<dim3(32, 1, 64), 512, GEMM_SMEM>>>(pW0eh, pW0el, pEh, pEl, 1024, pEmbW, 1024);

    for (int t = 0; t < 64; t++) {
        // LSTM layer 0: [feed|h0_prev] @ [Wfeed|Whh0]^T
        gemm3<<<dim3(32, 4, 1), 512, GEMM_SMEM>>>(pWc0h, pWc0l, pZ0h, pZ0l, 2048, pPart, 2048);
        lstm_cell<<<256, 256>>>(pPart, 4, pEmbW + (size_t)t * 4096 * 64, pB0,
                                pC0, pZ1h, pZ1l, 0, pZ0h, pZ0l, 1024);
        // LSTM layer 1
        gemm3<<<dim3(32, 4, 1), 512, GEMM_SMEM>>>(pWc1h, pWc1l, pZ1h, pZ1l, 2048, pPart, 2048);
        lstm_cell<<<256, 256>>>(pPart, 4, nullptr, pB1,
                                pC1, pZoh, pZol, 1024, pZ1h, pZ1l, 1024);
        // q = h1 @ W_in^T
        gemm3<<<dim3(8, 8, 1), 512, GEMM_SMEM>>>(pWinh, pWinl, pZoh + 1024, pZol + 1024,
                                                 2048, pPart, 1024);
        attention_k<<<64, 256>>>(pPart, 8, context, attns + (size_t)t * 64 * 64, pZoh, pZol);
        // attn_h = tanh([cvec|h1] @ W_out^T)
        gemm3<<<dim3(8, 8, 1), 512, GEMM_SMEM>>>(pWouth, pWoutl, pZoh, pZol,
                                                 2048, pPart, 2048);
        attn_out<<<256, 256>>>(pPart, 8, outs + (size_t)t * 64 * 1024, pZ0h, pZ0l);
    }
}

// round 6
// speedup vs baseline: 2.3764x; 1.1350x over previous
#include <cuda_runtime.h>
#include <cuda_bf16.h>
#include <cstdint>
#include <math.h>

typedef __nv_bfloat16 bf16;

// Shapes: T=64, B=64, S=64, E=1024, D=1024, G=4096
// Persistent kernel: 128 CTAs x 512 threads, one CTA per SM, global barriers.
// GEMM: out[n][b] split-K partials = sum_k W[n][k]*Z[b][k], 3-term hi/lo bf16 mma.sync.

#define NCTA 128

// ---------------- static device scratch ----------------
__device__ __align__(16) bf16 g_W0e_h[4096*1024], g_W0e_l[4096*1024];
__device__ __align__(16) bf16 g_Wc0_h[4096*2048], g_Wc0_l[4096*2048];
__device__ __align__(16) bf16 g_Wc1_h[4096*2048], g_Wc1_l[4096*2048];
__device__ __align__(16) bf16 g_Win_h[1024*1024], g_Win_l[1024*1024];
__device__ __align__(16) bf16 g_Wout_h[1024*2048], g_Wout_l[1024*2048];
__device__ __align__(16) bf16 g_embh[4096*1024],  g_embl[4096*1024];
__device__ __align__(16) float g_embW[64*4096*64];   // [t][n][b]
__device__ __align__(16) float g_part[16*1024*64 > 4*4096*64 ? 16*1024*64 : 4*4096*64];
__device__ __align__(16) bf16 g_Z0h[64*2048], g_Z0l[64*2048];  // [feed | h0_prev]
__device__ __align__(16) bf16 g_Z1h[64*2048], g_Z1l[64*2048];  // [h0_new | h1_prev]
__device__ __align__(16) bf16 g_Zoh[64*2048], g_Zol[64*2048];  // [cvec | h1_new]
__device__ __align__(16) float g_cT0[1024*64], g_cT1[1024*64];
__device__ __align__(16) float g_bias0[4096], g_bias1[4096];
__device__ int g_bar_cnt = 0;
__device__ int g_bar_phase = 0;

// ---------------- PTX helpers ----------------
__device__ __forceinline__ uint32_t smem_u32(const void* p) {
    uint32_t a;
    asm("{ .reg .u64 t; cvta.to.shared.u64 t, %1; cvt.u32.u64 %0, t; }" : "=r"(a) : "l"(p));
    return a;
}
__device__ __forceinline__ void ldm4(uint32_t* r, uint32_t a) {
    asm volatile("ldmatrix.sync.aligned.m8n8.x4.shared.b16 {%0,%1,%2,%3}, [%4];"
                 : "=r"(r[0]), "=r"(r[1]), "=r"(r[2]), "=r"(r[3]) : "r"(a));
}
__device__ __forceinline__ void mma_bf16(float* c, const uint32_t* a, uint32_t b0, uint32_t b1) {
    asm volatile("mma.sync.aligned.m16n8k16.row.col.f32.bf16.bf16.f32 "
                 "{%0,%1,%2,%3}, {%4,%5,%6,%7}, {%8,%9}, {%0,%1,%2,%3};"
                 : "+f"(c[0]), "+f"(c[1]), "+f"(c[2]), "+f"(c[3])
                 : "r"(a[0]), "r"(a[1]), "r"(a[2]), "r"(a[3]), "r"(b0), "r"(b1));
}
__device__ __forceinline__ void cpa16(uint32_t s, const void* g) {
    asm volatile("cp.async.cg.shared.global [%0], [%1], 16;" :: "r"(s), "l"(g));
}
#define CP_COMMIT() asm volatile("cp.async.commit_group;" ::: "memory")

__device__ __forceinline__ void hilo(float x, bf16& h, bf16& l) {
    h = __float2bfloat16(x);
    l = __float2bfloat16(x - __bfloat162float(h));
}

// global counter barrier; all NCTA CTAs co-resident (1 CTA/SM guaranteed by smem)
__device__ __forceinline__ void gsync(int& tgt) {
    __syncthreads();
    tgt++;
    if (threadIdx.x == 0) {
        __threadfence();
        if (atomicAdd(&g_bar_cnt, 1) == NCTA - 1) {
            atomicExch(&g_bar_cnt, 0);
            __threadfence();
            atomicAdd(&g_bar_phase, 1);
        } else {
            while (*(volatile int*)&g_bar_phase - tgt < 0) {}
            __threadfence();
        }
    }
    __syncthreads();
}

// ---------------- GEMM tile (device fn; 512 threads, 4x4 warp grid) ----------------
static constexpr int PITCH = 72;
static constexpr int WBYTES = 128 * PITCH * 2;
static constexpr int ZBYTES = 64 * PITCH * 2;
static constexpr int BUFBYTES = 2 * WBYTES + 2 * ZBYTES;  // 55296
static constexpr int GEMM_SMEM = 2 * BUFBYTES;            // 110592

__device__ __forceinline__ void gemm_tile(
    const bf16* __restrict__ Wh, const bf16* __restrict__ Wl,
    const bf16* __restrict__ Zh, const bf16* __restrict__ Zl,
    int ldz, float* __restrict__ out, int K,
    int n0, int k0, int chunks, char* dsm)
{
    const int tid  = threadIdx.x;
    const int lane = tid & 31, wid = tid >> 5;
    const int wm = wid >> 2, wn = wid & 3;
    const uint32_t sb = smem_u32(dsm);

    float acc[2][2][4];
#pragma unroll
    for (int mi = 0; mi < 2; mi++)
#pragma unroll
        for (int nj = 0; nj < 2; nj++)
#pragma unroll
            for (int q = 0; q < 4; q++) acc[mi][nj][q] = 0.f;

    auto stage = [&](int c) {
        const uint32_t S = sb + (c & 1) * BUFBYTES;
        const int kb = k0 + c * 64;
#pragma unroll
        for (int i = 0; i < 2; i++) {
            int idx = i * 512 + tid;
            int row = idx >> 3, cg = idx & 7;
            size_t g = (size_t)(n0 + row) * K + kb + cg * 8;
            uint32_t d = S + (row * PITCH + cg * 8) * 2;
            cpa16(d, Wh + g);
            cpa16(d + WBYTES, Wl + g);
        }
        {
            int row = tid >> 3, cg = tid & 7;
            size_t g = (size_t)row * ldz + kb + cg * 8;
            uint32_t d = S + 2 * WBYTES + (row * PITCH + cg * 8) * 2;
            cpa16(d, Zh + g);
            cpa16(d + ZBYTES, Zl + g);
        }
        CP_COMMIT();
    };

    stage(0);
    for (int c = 0; c < chunks; c++) {
        if (c + 1 < chunks) {
            stage(c + 1);
            asm volatile("cp.async.wait_group 1;" ::: "memory");
        } else {
            asm volatile("cp.async.wait_group 0;" ::: "memory");
        }
        __syncthreads();

        const uint32_t S = sb + (c & 1) * BUFBYTES;
        const uint32_t aw = S + ((wm * 32 + (lane & 15)) * PITCH + (lane >> 4) * 8) * 2;
        const uint32_t bz = S + 2 * WBYTES + ((wn * 16 + (lane & 15)) * PITCH + (lane >> 4) * 8) * 2;

#pragma unroll
        for (int ks = 0; ks < 4; ks++) {
            const uint32_t koff = ks * 32;
            uint32_t ah[2][4], al[2][4], bh[4], bl[4];
#pragma unroll
            for (int mi = 0; mi < 2; mi++) {
                uint32_t a = aw + mi * 16 * PITCH * 2 + koff;
                ldm4(ah[mi], a);
                ldm4(al[mi], a + WBYTES);
            }
            ldm4(bh, bz + koff);
            ldm4(bl, bz + koff + ZBYTES);
#pragma unroll
            for (int mi = 0; mi < 2; mi++)
#pragma unroll
                for (int nj = 0; nj < 2; nj++) {
                    mma_bf16(acc[mi][nj], ah[mi], bh[nj], bh[2 + nj]);
                    mma_bf16(acc[mi][nj], ah[mi], bl[nj], bl[2 + nj]);
                    mma_bf16(acc[mi][nj], al[mi], bh[nj], bh[2 + nj]);
                }
        }
        __syncthreads();
    }

#pragma unroll
    for (int mi = 0; mi < 2; mi++)
#pragma unroll
        for (int nj = 0; nj < 2; nj++) {
            int m = n0 + wm * 32 + mi * 16 + (lane >> 2);
            int b = wn * 16 + nj * 8 + (lane & 3) * 2;
            *(float2*)(out + (size_t)m * 64 + b) =
                make_float2(acc[mi][nj][0], acc[mi][nj][1]);
            *(float2*)(out + (size_t)(m + 8) * 64 + b) =
                make_float2(acc[mi][nj][2], acc[mi][nj][3]);
        }
}

// ---------------- cell phase (one element per thread) ----------------
__device__ __forceinline__ void cell_phase(
    int e, const float* __restrict__ part,
    const float* __restrict__ base, const float* __restrict__ bias,
    float* __restrict__ cT,
    bf16* hAh, bf16* hAl, int offA, bf16* hBh, bf16* hBl, int offB)
{
    int d = e >> 6, b = e & 63;
    float g[4];
#pragma unroll
    for (int j = 0; j < 4; j++) {
        float acc = bias[j * 1024 + d];
        if (base) acc += base[(size_t)j * 65536 + e];
#pragma unroll
        for (int ks = 0; ks < 4; ks++)
            acc += part[(size_t)ks * 262144 + (size_t)j * 65536 + e];
        g[j] = acc;
    }
    float ig = 1.f / (1.f + expf(-g[0]));
    float fg = 1.f / (1.f + expf(-g[1]));
    float gg = tanhf(g[2]);
    float og = 1.f / (1.f + expf(-g[3]));
    float cn = fg * cT[e] + ig * gg;
    float h  = og * tanhf(cn);
    cT[e] = cn;
    bf16 hh, hl;
    hilo(h, hh, hl);
    hAh[b * 2048 + offA + d] = hh; hAl[b * 2048 + offA + d] = hl;
    hBh[b * 2048 + offB + d] = hh; hBl[b * 2048 + offB + d] = hl;
}

// ---------------- persistent kernel ----------------
__global__ void __launch_bounds__(512) persistent_k(
    const float* __restrict__ ctx, float* __restrict__ outs, float* __restrict__ attns)
{
    extern __shared__ __align__(16) char dsm[];
    const int bi = blockIdx.x, tid = threadIdx.x;
    const int lane = tid & 31, w = tid >> 5;
    int tgt = *(volatile int*)&g_bar_phase;

    for (int t = 0; t < 64; t++) {
        // ---- Phase 1: LSTM0 GEMM: mtile=bi>>2 (32), ks=bi&3 (4), Kchunk=512 ----
        gemm_tile(g_Wc0_h, g_Wc0_l, g_Z0h, g_Z0l, 2048,
                  g_part + (size_t)(bi & 3) * 262144, 2048,
                  (bi >> 2) * 128, (bi & 3) * 512, 8, dsm);
        gsync(tgt);
        // ---- Phase 2: cell0 ----
        cell_phase(bi * 512 + tid, g_part, g_embW + (size_t)t * 262144, g_bias0,
                   g_cT0, g_Z1h, g_Z1l, 0, g_Z0h, g_Z0l, 1024);
        gsync(tgt);
        // ---- Phase 3: LSTM1 GEMM ----
        gemm_tile(g_Wc1_h, g_Wc1_l, g_Z1h, g_Z1l, 2048,
                  g_part + (size_t)(bi & 3) * 262144, 2048,
                  (bi >> 2) * 128, (bi & 3) * 512, 8, dsm);
        gsync(tgt);
        // ---- Phase 4: cell1 ----
        cell_phase(bi * 512 + tid, g_part, nullptr, g_bias1,
                   g_cT1, g_Zoh, g_Zol, 1024, g_Z1h, g_Z1l, 1024);
        gsync(tgt);
        // ---- Phase 5: q GEMM: mtile=bi>>4 (8), ks=bi&15 (16), Kchunk=64 ----
        gemm_tile(g_Win_h, g_Win_l, g_Zoh + 1024, g_Zol + 1024, 2048,
                  g_part + (size_t)(bi & 15) * 65536, 1024,
                  (bi >> 4) * 128, (bi & 15) * 64, 1, dsm);
        gsync(tgt);
        // ---- Phase 6: attention (CTAs 0..63, one per batch row) ----
        if (bi < 64) {
            const int b = bi;
            float* qs = (float*)dsm;          // 1024
            float* sc = qs + 1024;            // 64
            for (int d = tid; d < 1024; d += 512) {
                float acc = 0.f;
#pragma unroll
                for (int ks = 0; ks < 16; ks++)
                    acc += g_part[((size_t)ks * 1024 + d) * 64 + b];
                qs[d] = acc;
            }
            __syncthreads();
#pragma unroll
            for (int so = 0; so < 4; so++) {
                int s = w * 4 + so;
                const float* cr = ctx + ((size_t)s * 64 + b) * 1024;
                float acc = 0.f;
                for (int d = lane; d < 1024; d += 32) acc += qs[d] * cr[d];
#pragma unroll
                for (int off = 16; off; off >>= 1)
                    acc += __shfl_down_sync(0xffffffffu, acc, off);
                if (lane == 0) sc[s] = acc;
            }
            __syncthreads();
            if (tid < 32) {
                float v0 = sc[tid], v1 = sc[tid + 32];
                float m = fmaxf(v0, v1);
#pragma unroll
                for (int off = 16; off; off >>= 1)
                    m = fmaxf(m, __shfl_xor_sync(0xffffffffu, m, off));
                float e0 = expf(v0 - m), e1 = expf(v1 - m);
                float s = e0 + e1;
#pragma unroll
                for (int off = 16; off; off >>= 1)
                    s += __shfl_xor_sync(0xffffffffu, s, off);
                float inv = 1.f / s;
                float a0 = e0 * inv, a1 = e1 * inv;
                sc[tid] = a0; sc[tid + 32] = a1;
                float* at = attns + (size_t)t * 4096 + b * 64;
                at[tid] = a0; at[tid + 32] = a1;
            }
            __syncthreads();
            for (int d = tid; d < 1024; d += 512) {
                float acc = 0.f;
#pragma unroll 8
                for (int s = 0; s < 64; s++)
                    acc += sc[s] * ctx[((size_t)s * 64 + b) * 1024 + d];
                bf16 hh, hl;
                hilo(acc, hh, hl);
                g_Zoh[b * 2048 + d] = hh;
                g_Zol[b * 2048 + d] = hl;
            }
        }
        gsync(tgt);
        // ---- Phase 7: out GEMM: mtile=bi>>4 (8), ks=bi&15 (16), Kchunk=128 ----
        gemm_tile(g_Wout_h, g_Wout_l, g_Zoh, g_Zol, 2048,
                  g_part + (size_t)(bi & 15) * 65536, 2048,
                  (bi >> 4) * 128, (bi & 15) * 128, 2, dsm);
        gsync(tgt);
        // ---- Phase 8: tanh + outputs + next input feed ----
        {
            int e = bi * 512 + tid;
            int d = e >> 6, b = e & 63;
            float acc = 0.f;
#pragma unroll
            for (int ks = 0; ks < 16; ks++)
                acc += g_part[(size_t)ks * 65536 + e];
            float h = tanhf(acc);
            outs[(size_t)t * 65536 + b * 1024 + d] = h;
            bf16 hh, hl;
            hilo(h, hh, hl);
            g_Z0h[b * 2048 + d] = hh;
            g_Z0l[b * 2048 + d] = hl;
        }
        gsync(tgt);
    }
}

// ---------------- embW precompute GEMM (standalone, 2048 CTAs) ----------------
__global__ void __launch_bounds__(512) gemm_pre(float* __restrict__ out)
{
    extern __shared__ __align__(16) char dsm[];
    // grid: (32 mtiles, 64 t)
    gemm_tile(g_W0e_h, g_W0e_l,
              g_embh + (size_t)blockIdx.y * 65536, g_embl + (size_t)blockIdx.y * 65536,
              1024, out + (size_t)blockIdx.y * 262144, 1024,
              blockIdx.x * 128, 0, 16, dsm);
}

// ---------------- init state ----------------
__global__ void init_state(const float* __restrict__ input_feed,
                           const float* __restrict__ h0, const float* __restrict__ c0)
{
    int e = blockIdx.x * blockDim.x + threadIdx.x;  // 65536
    int b = e >> 10, d = e & 1023;
    bf16 hh, hl;
    hilo(input_feed[e], hh, hl);
    g_Z0h[b * 2048 + d] = hh; g_Z0l[b * 2048 + d] = hl;
    hilo(h0[e], hh, hl);
    g_Z0h[b * 2048 + 1024 + d] = hh; g_Z0l[b * 2048 + 1024 + d] = hl;
    hilo(h0[65536 + e], hh, hl);
    g_Z1h[b * 2048 + 1024 + d] = hh; g_Z1l[b * 2048 + 1024 + d] = hl;
    g_cT0[d * 64 + b] = c0[e];
    g_cT1[d * 64 + b] = c0[65536 + e];
}

// ---------------- weight prep ----------------
__global__ void prep_w(const float* __restrict__ W_ih0, const float* __restrict__ W_hh0,
                       const float* __restrict__ W_ih1, const float* __restrict__ W_hh1,
                       const float* __restrict__ W_in,  const float* __restrict__ W_out,
                       const float* __restrict__ emb,
                       const float* __restrict__ b_ih0, const float* __restrict__ b_hh0,
                       const float* __restrict__ b_ih1, const float* __restrict__ b_hh1)
{
    size_t stride = (size_t)gridDim.x * blockDim.x;
    for (size_t i = (size_t)blockIdx.x * blockDim.x + threadIdx.x;
         i < 4096ull * 2048ull; i += stride) {
        size_t n = i >> 11, k = i & 2047;
        float v0 = (k < 1024) ? W_ih0[n * 2048 + 1024 + k] : W_hh0[n * 1024 + (k - 1024)];
        hilo(v0, g_Wc0_h[i], g_Wc0_l[i]);
        float v1 = (k < 1024) ? W_ih1[n * 1024 + k] : W_hh1[n * 1024 + (k - 1024)];
        hilo(v1, g_Wc1_h[i], g_Wc1_l[i]);
        if (n < 1024) hilo(W_out[i], g_Wout_h[i], g_Wout_l[i]);
        if (i < 4096ull * 1024ull) {
            size_t nn = i >> 10, kk = i & 1023;
            hilo(W_ih0[nn * 2048 + kk], g_W0e_h[i], g_W0e_l[i]);
            hilo(emb[i], g_embh[i], g_embl[i]);
        }
        if (i < 1024ull * 1024ull) hilo(W_in[i], g_Win_h[i], g_Win_l[i]);
        if (i < 4096) {
            g_bias0[i] = b_ih0[i] + b_hh0[i];
            g_bias1[i] = b_ih1[i] + b_hh1[i];
        }
    }
}

// ---------------- host orchestration ----------------
extern "C" void kernel_launch(void* const* d_in, const int* in_sizes, int n_in,
                              void* d_out, int out_size)
{
    (void)in_sizes; (void)n_in; (void)out_size;
    const float* emb        = (const float*)d_in[0];
    const float* context    = (const float*)d_in[1];
    const float* input_feed = (const float*)d_in[2];
    const float* h0         = (const float*)d_in[3];
    const float* c0         = (const float*)d_in[4];
    const float* W_ih0      = (const float*)d_in[5];
    const float* W_hh0      = (const float*)d_in[6];
    const float* b_ih0      = (const float*)d_in[7];
    const float* b_hh0      = (const float*)d_in[8];
    const float* W_ih1      = (const float*)d_in[9];
    const float* W_hh1      = (const float*)d_in[10];
    const float* b_ih1      = (const float*)d_in[11];
    const float* b_hh1      = (const float*)d_in[12];
    const float* W_in       = (const float*)d_in[13];
    const float* W_out      = (const float*)d_in[14];

    float* outs  = (float*)d_out;
    float* attns = outs + 64 * 64 * 1024;

    static bool attr_set = false;
    if (!attr_set) {
        cudaFuncSetAttribute(persistent_k, cudaFuncAttributeMaxDynamicSharedMemorySize, GEMM_SMEM);
        cudaFuncSetAttribute(gemm_pre, cudaFuncAttributeMaxDynamicSharedMemorySize, GEMM_SMEM);
        attr_set = true;
    }

    float* pEmbW;
    cudaGetSymbolAddress((void**)&pEmbW, g_embW);

    prep_w<<<4096, 256>>>(W_ih0, W_hh0, W_ih1, W_hh1, W_in, W_out, emb,
                          b_ih0, b_hh0, b_ih1, b_hh1);
    init_state<<<256, 256>>>(input_feed, h0, c0);
    gemm_pre<<<dim3(32, 64), 512, GEMM_SMEM>>>(pEmbW);
    persistent_k<<<NCTA, 512, GEMM_SMEM>>>(context, outs, attns);
}

// round 7
// speedup vs baseline: 2.4938x; 1.0494x over previous
#include <cuda_runtime.h>
#include <cuda_bf16.h>
#include <cstdint>
#include <math.h>

typedef __nv_bfloat16 bf16;

// Shapes: T=64, B=64, S=64, E=1024, D=1024, G=4096
// Persistent kernel: 128 CTAs x 512 threads, one CTA per SM, global barriers.
// GEMM: out[n][b] split-K partials = sum_k W[n][k]*Z[b][k], 3-term hi/lo bf16 mma.sync.
// Attention refactor: scores[b,s] = h1[b] . ctxW[s,b], ctxW precomputed once.

#define NCTA 128

// ---------------- static device scratch ----------------
__device__ __align__(16) bf16 g_W0e_h[4096*1024], g_W0e_l[4096*1024];
__device__ __align__(16) bf16 g_Wc0_h[4096*2048], g_Wc0_l[4096*2048];
__device__ __align__(16) bf16 g_Wc1_h[4096*2048], g_Wc1_l[4096*2048];
__device__ __align__(16) bf16 g_WinT_h[1024*1024], g_WinT_l[1024*1024];  // W_in^T: [e][d]
__device__ __align__(16) bf16 g_Wout_h[1024*2048], g_Wout_l[1024*2048];
__device__ __align__(16) bf16 g_embh[4096*1024],  g_embl[4096*1024];
__device__ __align__(16) bf16 g_ctxRh[4096*1024], g_ctxRl[4096*1024];   // ctx rows re-packed per bpair
__device__ __align__(16) float g_ctxWT[64*64*1024];  // [(bpair*16+eblk)][srow(128)][elocal(64)]
__device__ __align__(16) float g_embW[64*4096*64];   // [t][n][b]
__device__ __align__(16) float g_part[24*1024*64 > 4*4096*64 ? 24*1024*64 : 4*4096*64];
__device__ __align__(16) bf16 g_Z0h[64*2048], g_Z0l[64*2048];  // [feed | h0_prev]
__device__ __align__(16) bf16 g_Z1h[64*2048], g_Z1l[64*2048];  // [h0_new | h1_prev]
__device__ __align__(16) bf16 g_Zoh[64*2048], g_Zol[64*2048];  // [cvec | h1_new]
__device__ __align__(16) float g_h1f[64*1024];                 // fp32 h1 [b][d]
__device__ __align__(16) float g_cT0[1024*64], g_cT1[1024*64];
__device__ __align__(16) float g_bias0[4096], g_bias1[4096];
__device__ int g_bar_cnt = 0;
__device__ int g_bar_phase = 0;

// ---------------- PTX helpers ----------------
__device__ __forceinline__ uint32_t smem_u32(const void* p) {
    uint32_t a;
    asm("{ .reg .u64 t; cvta.to.shared.u64 t, %1; cvt.u32.u64 %0, t; }" : "=r"(a) : "l"(p));
    return a;
}
__device__ __forceinline__ void ldm4(uint32_t* r, uint32_t a) {
    asm volatile("ldmatrix.sync.aligned.m8n8.x4.shared.b16 {%0,%1,%2,%3}, [%4];"
                 : "=r"(r[0]), "=r"(r[1]), "=r"(r[2]), "=r"(r[3]) : "r"(a));
}
__device__ __forceinline__ void mma_bf16(float* c, const uint32_t* a, uint32_t b0, uint32_t b1) {
    asm volatile("mma.sync.aligned.m16n8k16.row.col.f32.bf16.bf16.f32 "
                 "{%0,%1,%2,%3}, {%4,%5,%6,%7}, {%8,%9}, {%0,%1,%2,%3};"
                 : "+f"(c[0]), "+f"(c[1]), "+f"(c[2]), "+f"(c[3])
                 : "r"(a[0]), "r"(a[1]), "r"(a[2]), "r"(a[3]), "r"(b0), "r"(b1));
}
__device__ __forceinline__ void cpa16(uint32_t s, const void* g) {
    asm volatile("cp.async.cg.shared.global [%0], [%1], 16;" :: "r"(s), "l"(g));
}
#define CP_COMMIT() asm volatile("cp.async.commit_group;" ::: "memory")

__device__ __forceinline__ void hilo(float x, bf16& h, bf16& l) {
    h = __float2bfloat16(x);
    l = __float2bfloat16(x - __bfloat162float(h));
}

// global counter barrier; all NCTA CTAs co-resident (1 CTA/SM by smem)
__device__ __forceinline__ void gsync(int& tgt) {
    __syncthreads();
    tgt++;
    if (threadIdx.x == 0) {
        __threadfence();
        if (atomicAdd(&g_bar_cnt, 1) == NCTA - 1) {
            atomicExch(&g_bar_cnt, 0);
            __threadfence();
            atomicAdd(&g_bar_phase, 1);
        } else {
            while (*(volatile int*)&g_bar_phase - tgt < 0) {}
            __threadfence();
        }
    }
    __syncthreads();
}

// ---------------- GEMM tile (device fn; 512 threads, 4x4 warp grid) ----------------
static constexpr int PITCH = 72;
static constexpr int WBYTES = 128 * PITCH * 2;
static constexpr int ZBYTES = 64 * PITCH * 2;
static constexpr int BUFBYTES = 2 * WBYTES + 2 * ZBYTES;  // 55296
static constexpr int GEMM_SMEM = 2 * BUFBYTES;            // 110592

__device__ __forceinline__ void gemm_tile(
    const bf16* __restrict__ Wh, const bf16* __restrict__ Wl,
    const bf16* __restrict__ Zh, const bf16* __restrict__ Zl,
    int ldz, float* __restrict__ out, int K,
    int n0, int k0, int chunks, char* dsm)
{
    const int tid  = threadIdx.x;
    const int lane = tid & 31, wid = tid >> 5;
    const int wm = wid >> 2, wn = wid & 3;
    const uint32_t sb = smem_u32(dsm);

    float acc[2][2][4];
#pragma unroll
    for (int mi = 0; mi < 2; mi++)
#pragma unroll
        for (int nj = 0; nj < 2; nj++)
#pragma unroll
            for (int q = 0; q < 4; q++) acc[mi][nj][q] = 0.f;

    auto stage = [&](int c) {
        const uint32_t S = sb + (c & 1) * BUFBYTES;
        const int kb = k0 + c * 64;
#pragma unroll
        for (int i = 0; i < 2; i++) {
            int idx = i * 512 + tid;
            int row = idx >> 3, cg = idx & 7;
            size_t g = (size_t)(n0 + row) * K + kb + cg * 8;
            uint32_t d = S + (row * PITCH + cg * 8) * 2;
            cpa16(d, Wh + g);
            cpa16(d + WBYTES, Wl + g);
        }
        {
            int row = tid >> 3, cg = tid & 7;
            size_t g = (size_t)row * ldz + kb + cg * 8;
            uint32_t d = S + 2 * WBYTES + (row * PITCH + cg * 8) * 2;
            cpa16(d, Zh + g);
            cpa16(d + ZBYTES, Zl + g);
        }
        CP_COMMIT();
    };

    stage(0);
    for (int c = 0; c < chunks; c++) {
        if (c + 1 < chunks) {
            stage(c + 1);
            asm volatile("cp.async.wait_group 1;" ::: "memory");
        } else {
            asm volatile("cp.async.wait_group 0;" ::: "memory");
        }
        __syncthreads();

        const uint32_t S = sb + (c & 1) * BUFBYTES;
        const uint32_t aw = S + ((wm * 32 + (lane & 15)) * PITCH + (lane >> 4) * 8) * 2;
        const uint32_t bz = S + 2 * WBYTES + ((wn * 16 + (lane & 15)) * PITCH + (lane >> 4) * 8) * 2;

#pragma unroll
        for (int ks = 0; ks < 4; ks++) {
            const uint32_t koff = ks * 32;
            uint32_t ah[2][4], al[2][4], bh[4], bl[4];
#pragma unroll
            for (int mi = 0; mi < 2; mi++) {
                uint32_t a = aw + mi * 16 * PITCH * 2 + koff;
                ldm4(ah[mi], a);
                ldm4(al[mi], a + WBYTES);
            }
            ldm4(bh, bz + koff);
            ldm4(bl, bz + koff + ZBYTES);
#pragma unroll
            for (int mi = 0; mi < 2; mi++)
#pragma unroll
                for (int nj = 0; nj < 2; nj++) {
                    mma_bf16(acc[mi][nj], ah[mi], bh[nj], bh[2 + nj]);
                    mma_bf16(acc[mi][nj], ah[mi], bl[nj], bl[2 + nj]);
                    mma_bf16(acc[mi][nj], al[mi], bh[nj], bh[2 + nj]);
                }
        }
        __syncthreads();
    }

#pragma unroll
    for (int mi = 0; mi < 2; mi++)
#pragma unroll
        for (int nj = 0; nj < 2; nj++) {
            int m = n0 + wm * 32 + mi * 16 + (lane >> 2);
            int b = wn * 16 + nj * 8 + (lane & 3) * 2;
            *(float2*)(out + (size_t)m * 64 + b) =
                make_float2(acc[mi][nj][0], acc[mi][nj][1]);
            *(float2*)(out + (size_t)(m + 8) * 64 + b) =
                make_float2(acc[mi][nj][2], acc[mi][nj][3]);
        }
}

// ---------------- cell phase (one element per thread) ----------------
__device__ __forceinline__ void cell_phase(
    int e, const float* __restrict__ part,
    const float* __restrict__ base, const float* __restrict__ bias,
    float* __restrict__ cT,
    bf16* hAh, bf16* hAl, int offA, bf16* hBh, bf16* hBl, int offB,
    float* __restrict__ h1f)
{
    int d = e >> 6, b = e & 63;
    float g[4];
#pragma unroll
    for (int j = 0; j < 4; j++) {
        float acc = bias[j * 1024 + d];
        if (base) acc += base[(size_t)j * 65536 + e];
#pragma unroll
        for (int ks = 0; ks < 4; ks++)
            acc += part[(size_t)ks * 262144 + (size_t)j * 65536 + e];
        g[j] = acc;
    }
    float ig = 1.f / (1.f + expf(-g[0]));
    float fg = 1.f / (1.f + expf(-g[1]));
    float gg = tanhf(g[2]);
    float og = 1.f / (1.f + expf(-g[3]));
    float cn = fg * cT[e] + ig * gg;
    float h  = og * tanhf(cn);
    cT[e] = cn;
    bf16 hh, hl;
    hilo(h, hh, hl);
    hAh[b * 2048 + offA + d] = hh; hAl[b * 2048 + offA + d] = hl;
    hBh[b * 2048 + offB + d] = hh; hBl[b * 2048 + offB + d] = hl;
    if (h1f) h1f[b * 1024 + d] = h;
}

// ---------------- persistent kernel ----------------
__global__ void __launch_bounds__(512) persistent_k(
    const float* __restrict__ ctx, float* __restrict__ outs, float* __restrict__ attns)
{
    extern __shared__ __align__(16) char dsm[];
    const int bi = blockIdx.x, tid = threadIdx.x;
    const int lane = tid & 31, w = tid >> 5;
    int tgt = *(volatile int*)&g_bar_phase;

    for (int t = 0; t < 64; t++) {
        // ---- P1: LSTM0 GEMM: mtile=bi>>2 (32), ks=bi&3 (4), Kchunk=512 ----
        gemm_tile(g_Wc0_h, g_Wc0_l, g_Z0h, g_Z0l, 2048,
                  g_part + (size_t)(bi & 3) * 262144, 2048,
                  (bi >> 2) * 128, (bi & 3) * 512, 8, dsm);
        gsync(tgt);
        // ---- P2: cell0 ----
        cell_phase(bi * 512 + tid, g_part, g_embW + (size_t)t * 262144, g_bias0,
                   g_cT0, g_Z1h, g_Z1l, 0, g_Z0h, g_Z0l, 1024, nullptr);
        gsync(tgt);
        // ---- P3: LSTM1 GEMM ----
        gemm_tile(g_Wc1_h, g_Wc1_l, g_Z1h, g_Z1l, 2048,
                  g_part + (size_t)(bi & 3) * 262144, 2048,
                  (bi >> 2) * 128, (bi & 3) * 512, 8, dsm);
        gsync(tgt);
        // ---- P4: cell1 (also emits fp32 h1) ----
        cell_phase(bi * 512 + tid, g_part, nullptr, g_bias1,
                   g_cT1, g_Zoh, g_Zol, 1024, g_Z1h, g_Z1l, 1024, g_h1f);
        gsync(tgt);
        // ---- P5: CTAs 0-63 attention; CTAs 64-127 out-GEMM h1 half ----
        if (bi < 64) {
            const int b = bi;
            float* qs = (float*)dsm;          // 1024 fp32 h1[b]
            float* sc = qs + 1024;            // 64 scores
            for (int d = tid; d < 1024; d += 512) qs[d] = g_h1f[b * 1024 + d];
            __syncthreads();
            const int bpair = b >> 1, brow = (b & 1) * 64;
#pragma unroll
            for (int so = 0; so < 4; so++) {
                int s = w * 4 + so;
                float acc = 0.f;
#pragma unroll
                for (int eblk = 0; eblk < 16; eblk++) {
                    const float* cwp = g_ctxWT +
                        ((size_t)(bpair * 16 + eblk) * 128 + brow + s) * 64;
                    acc += qs[eblk * 64 + lane] * cwp[lane];
                    acc += qs[eblk * 64 + 32 + lane] * cwp[32 + lane];
                }
#pragma unroll
                for (int off = 16; off; off >>= 1)
                    acc += __shfl_down_sync(0xffffffffu, acc, off);
                if (lane == 0) sc[s] = acc;
            }
            __syncthreads();
            if (tid < 32) {
                float v0 = sc[tid], v1 = sc[tid + 32];
                float m = fmaxf(v0, v1);
#pragma unroll
                for (int off = 16; off; off >>= 1)
                    m = fmaxf(m, __shfl_xor_sync(0xffffffffu, m, off));
                float e0 = expf(v0 - m), e1 = expf(v1 - m);
                float s = e0 + e1;
#pragma unroll
                for (int off = 16; off; off >>= 1)
                    s += __shfl_xor_sync(0xffffffffu, s, off);
                float inv = 1.f / s;
                float a0 = e0 * inv, a1 = e1 * inv;
                sc[tid] = a0; sc[tid + 32] = a1;
                float* at = attns + (size_t)t * 4096 + b * 64;
                at[tid] = a0; at[tid + 32] = a1;
            }
            __syncthreads();
            for (int d = tid; d < 1024; d += 512) {
                float acc = 0.f;
#pragma unroll 8
                for (int s = 0; s < 64; s++)
                    acc += sc[s] * ctx[((size_t)s * 64 + b) * 1024 + d];
                bf16 hh, hl;
                hilo(acc, hh, hl);
                g_Zoh[b * 2048 + d] = hh;
                g_Zol[b * 2048 + d] = hl;
            }
        } else {
            const int idx = bi - 64;                  // 0..63
            const int mt = idx >> 3, ks = idx & 7;    // 8 mtiles x 8 ksplits
            gemm_tile(g_Wout_h, g_Wout_l, g_Zoh, g_Zol, 2048,
                      g_part + (size_t)(16 + ks) * 65536, 2048,
                      mt * 128, 1024 + ks * 128, 2, dsm);
        }
        gsync(tgt);
        // ---- P6: out GEMM cvec half: mtile=bi>>4 (8), ks=bi&15 (16), 1 chunk ----
        gemm_tile(g_Wout_h, g_Wout_l, g_Zoh, g_Zol, 2048,
                  g_part + (size_t)(bi & 15) * 65536, 2048,
                  (bi >> 4) * 128, (bi & 15) * 64, 1, dsm);
        gsync(tgt);
        // ---- P7: reduce 24 slices + tanh + outputs + next input feed ----
        {
            int e = bi * 512 + tid;
            int d = e >> 6, b = e & 63;
            float acc = 0.f;
#pragma unroll
            for (int ks = 0; ks < 24; ks++)
                acc += g_part[(size_t)ks * 65536 + e];
            float h = tanhf(acc);
            outs[(size_t)t * 65536 + b * 1024 + d] = h;
            bf16 hh, hl;
            hilo(h, hh, hl);
            g_Z0h[b * 2048 + d] = hh;
            g_Z0l[b * 2048 + d] = hl;
        }
        gsync(tgt);
    }
}

// ---------------- embW precompute GEMM (standalone, 2048 CTAs) ----------------
__global__ void __launch_bounds__(512) gemm_pre(float* __restrict__ out)
{
    extern __shared__ __align__(16) char dsm[];
    gemm_tile(g_W0e_h, g_W0e_l,
              g_embh + (size_t)blockIdx.y * 65536, g_embl + (size_t)blockIdx.y * 65536,
              1024, out + (size_t)blockIdx.y * 262144, 1024,
              blockIdx.x * 128, 0, 16, dsm);
}

// ---------------- ctxW precompute: out[(bpair,eblk)][srow][elocal] ----------------
__global__ void __launch_bounds__(512) ctxw_pre(float* __restrict__ out)
{
    extern __shared__ __align__(16) char dsm[];
    const int bpair = blockIdx.x;   // 32
    const int eblk  = blockIdx.y;   // 16
    gemm_tile(g_ctxRh + (size_t)bpair * 131072, g_ctxRl + (size_t)bpair * 131072,
              g_WinT_h + (size_t)eblk * 65536, g_WinT_l + (size_t)eblk * 65536,
              1024, out + ((size_t)bpair * 16 + eblk) * 8192, 1024,
              0, 0, 16, dsm);
}

// ---------------- init state ----------------
__global__ void init_state(const float* __restrict__ input_feed,
                           const float* __restrict__ h0, const float* __restrict__ c0)
{
    int e = blockIdx.x * blockDim.x + threadIdx.x;  // 65536
    int b = e >> 10, d = e & 1023;
    bf16 hh, hl;
    hilo(input_feed[e], hh, hl);
    g_Z0h[b * 2048 + d] = hh; g_Z0l[b * 2048 + d] = hl;
    hilo(h0[e], hh, hl);
    g_Z0h[b * 2048 + 1024 + d] = hh; g_Z0l[b * 2048 + 1024 + d] = hl;
    hilo(h0[65536 + e], hh, hl);
    g_Z1h[b * 2048 + 1024 + d] = hh; g_Z1l[b * 2048 + 1024 + d] = hl;
    g_cT0[d * 64 + b] = c0[e];
    g_cT1[d * 64 + b] = c0[65536 + e];
}

// ---------------- weight prep ----------------
__global__ void prep_w(const float* __restrict__ W_ih0, const float* __restrict__ W_hh0,
                       const float* __restrict__ W_ih1, const float* __restrict__ W_hh1,
                       const float* __restrict__ W_in,  const float* __restrict__ W_out,
                       const float* __restrict__ emb,   const float* __restrict__ ctx,
                       const float* __restrict__ b_ih0, const float* __restrict__ b_hh0,
                       const float* __restrict__ b_ih1, const float* __restrict__ b_hh1)
{
    size_t stride = (size_t)gridDim.x * blockDim.x;
    for (size_t i = (size_t)blockIdx.x * blockDim.x + threadIdx.x;
         i < 4096ull * 2048ull; i += stride) {
        size_t n = i >> 11, k = i & 2047;
        float v0 = (k < 1024) ? W_ih0[n * 2048 + 1024 + k] : W_hh0[n * 1024 + (k - 1024)];
        hilo(v0, g_Wc0_h[i], g_Wc0_l[i]);
        float v1 = (k < 1024) ? W_ih1[n * 1024 + k] : W_hh1[n * 1024 + (k - 1024)];
        hilo(v1, g_Wc1_h[i], g_Wc1_l[i]);
        if (n < 1024) hilo(W_out[i], g_Wout_h[i], g_Wout_l[i]);
        if (i < 4096ull * 1024ull) {
            size_t nn = i >> 10, kk = i & 1023;
            hilo(W_ih0[nn * 2048 + kk], g_W0e_h[i], g_W0e_l[i]);
            hilo(emb[i], g_embh[i], g_embl[i]);
            // ctx re-pack: i = (s*64+b)*1024 + d -> row (b&1)*64+s of bpair b>>1
            size_t b = (i >> 10) & 63, s = i >> 16, d = i & 1023;
            size_t ri = ((b >> 1) * 128 + (b & 1) * 64 + s) * 1024 + d;
            hilo(ctx[i], g_ctxRh[ri], g_ctxRl[ri]);
        }
        if (i < 1024ull * 1024ull) {
            // W_in transpose: i = d*1024 + e -> WinT[e][d]
            size_t ti = (i & 1023) * 1024 + (i >> 10);
            hilo(W_in[i], g_WinT_h[ti], g_WinT_l[ti]);
        }
        if (i < 4096) {
            g_bias0[i] = b_ih0[i] + b_hh0[i];
            g_bias1[i] = b_ih1[i] + b_hh1[i];
        }
    }
}

// ---------------- host orchestration ----------------
extern "C" void kernel_launch(void* const* d_in, const int* in_sizes, int n_in,
                              void* d_out, int out_size)
{
    (void)in_sizes; (void)n_in; (void)out_size;
    const float* emb        = (const float*)d_in[0];
    const float* context    = (const float*)d_in[1];
    const float* input_feed = (const float*)d_in[2];
    const float* h0         = (const float*)d_in[3];
    const float* c0         = (const float*)d_in[4];
    const float* W_ih0      = (const float*)d_in[5];
    const float* W_hh0      = (const float*)d_in[6];
    const float* b_ih0      = (const float*)d_in[7];
    const float* b_hh0      = (const float*)d_in[8];
    const float* W_ih1      = (const float*)d_in[9];
    const float* W_hh1      = (const float*)d_in[10];
    const float* b_ih1      = (const float*)d_in[11];
    const float* b_hh1      = (const float*)d_in[12];
    const float* W_in       = (const float*)d_in[13];
    const float* W_out      = (const float*)d_in[14];

    float* outs  = (float*)d_out;
    float* attns = outs + 64 * 64 * 1024;

    static bool attr_set = false;
    if (!attr_set) {
        cudaFuncSetAttribute(persistent_k, cudaFuncAttributeMaxDynamicSharedMemorySize, GEMM_SMEM);
        cudaFuncSetAttribute(gemm_pre, cudaFuncAttributeMaxDynamicSharedMemorySize, GEMM_SMEM);
        cudaFuncSetAttribute(ctxw_pre, cudaFuncAttributeMaxDynamicSharedMemorySize, GEMM_SMEM);
        attr_set = true;
    }

    float *pEmbW, *pCtxWT;
    cudaGetSymbolAddress((void**)&pEmbW, g_embW);
    cudaGetSymbolAddress((void**)&pCtxWT, g_ctxWT);

    prep_w<<<4096, 256>>>(W_ih0, W_hh0, W_ih1, W_hh1, W_in, W_out, emb, context,
                          b_ih0, b_hh0, b_ih1, b_hh1);
    init_state<<<256, 256>>>(input_feed, h0, c0);
    ctxw_pre<<<dim3(32, 16), 512, GEMM_SMEM>>>(pCtxWT);
    gemm_pre<<<dim3(32, 64), 512, GEMM_SMEM>>>(pEmbW);
    persistent_k<<<NCTA, 512, GEMM_SMEM>>>(context, outs, attns);
}